// round 4
// baseline (speedup 1.0000x reference)
#include <cuda_runtime.h>
#include <cuda_fp16.h>

// Problem constants (fixed by the reference setup)
#define B_ 4
#define C_ 3
#define H_ 512
#define W_ 960
#define HW_ (H_ * W_)

// Tile geometry: 64x16 pixels per block, 256 threads, 4 pixels/thread (along y)
#define TW 64
#define TH 16
#define SW (TW + 13)          // 77 cols: halo 6 left, 7 right
#define SH (TH + 13)          // 29 rows: halo 6 top, 7 bottom
#define SPLANE (SW * SH)      // 2233 texels

__global__ void __launch_bounds__(256, 5)
fi_tiled_h4o_kernel(const float* __restrict__ inp,
                    const float* __restrict__ flow,
                    const float* __restrict__ filt,
                    float* __restrict__ out)
{
    // one 8-byte texel per pixel: (half c0, half c1, half c2, pad)
    __shared__ uint2 sm[SPLANE];   // 17.9 KB

    const int x0 = blockIdx.x * TW;
    const int y0 = blockIdx.y * TH;
    const int b  = blockIdx.z;
    const int tid = threadIdx.x;

    const float* __restrict__ ibase = inp + (size_t)b * C_ * HW_;

    // ---- stage tile + halo into smem (border clamp baked in, fp32 -> fp16x3) ----
    #pragma unroll 3
    for (int idx = tid; idx < SPLANE; idx += 256) {
        const int j = idx / SW;
        const int i = idx - j * SW;
        const int gy = min(max(y0 - 6 + j, 0), H_ - 1);
        const int gx = min(max(x0 - 6 + i, 0), W_ - 1);
        const int g  = gy * W_ + gx;
        const float v0 = ibase[g];
        const float v1 = ibase[g + HW_];
        const float v2 = ibase[g + 2 * HW_];
        __half2 h01 = __floats2half2_rn(v0, v1);
        __half2 h2p = __floats2half2_rn(v2, 0.0f);
        uint2 u;
        u.x = *reinterpret_cast<unsigned*>(&h01);
        u.y = *reinterpret_cast<unsigned*>(&h2p);
        sm[idx] = u;
    }
    __syncthreads();

    const int x   = x0 + (tid & 63);
    const int tyg = tid >> 6;            // 0..3

    const float* __restrict__ flowx = flow + ((size_t)b * 2 + 0) * HW_;
    const float* __restrict__ flowy = flow + ((size_t)b * 2 + 1) * HW_;
    const float* __restrict__ fbb   = filt + (size_t)b * 16 * HW_;
    float* __restrict__ obb         = out  + (size_t)b * C_ * HW_;

    #pragma unroll 1
    for (int k = 0; k < 4; k++) {
        const int y   = y0 + tyg * 4 + k;
        const int pix = y * W_ + x;

        const float fx = flowx[pix];
        const float fy = flowy[pix];
        const float x2 = (float)x + fx;
        const float y2 = (float)y + fy;

        const bool valid =
            (x2 >= 0.0f) && (x2 <= (float)(W_ - 1)) &&
            (y2 >= 0.0f) && (y2 <= (float)(H_ - 1)) &&
            (fabsf(fx) < (float)W_ * 0.5f) &&
            (fabsf(fy) < (float)H_ * 0.5f);

        float* ob = obb + pix;
        if (!valid) {
            ob[0] = 0.0f; ob[HW_] = 0.0f; ob[2 * HW_] = 0.0f;
            continue;
        }

        const int   ix = (int)floorf(x2);
        const int   iy = (int)floorf(y2);
        const float a  = x2 - (float)ix;
        const float bt = y2 - (float)iy;

        const float wTL = (1.0f - a) * (1.0f - bt);
        const float wTR = a * (1.0f - bt);
        const float wBL = (1.0f - a) * bt;
        const float wBR = a * bt;

        // ---- 5x5 effective stencil = conv(filter_4x4, bilinear_2x2) ----
        float w5[5][5];
        #pragma unroll
        for (int r = 0; r < 5; r++)
            #pragma unroll
            for (int c = 0; c < 5; c++) w5[r][c] = 0.0f;

        const float* fb = fbb + pix;
        #pragma unroll
        for (int dj = 0; dj < 4; dj++) {
            #pragma unroll
            for (int di = 0; di < 4; di++) {
                const float f = __ldg(fb + (dj * 4 + di) * HW_);
                w5[dj    ][di    ] += f * wTL;
                w5[dj    ][di + 1] += f * wTR;
                w5[dj + 1][di    ] += f * wBL;
                w5[dj + 1][di + 1] += f * wBR;
            }
        }

        float r0 = 0.0f, r1 = 0.0f, r2 = 0.0f;

        const int ly = iy - y0 + 5;   // smem row of window top (r=0)
        const int lx = ix - x0 + 5;   // smem col of window left (c=0)

        if (ly >= 0 && ly <= SH - 5 && lx >= 0 && lx <= SW - 5) {
            // ---- fast path: 25 taps, one LDS.64 each (3 channels packed fp16) ----
            const uint2* s0 = sm + ly * SW + lx;
            #pragma unroll
            for (int r = 0; r < 5; r++) {
                #pragma unroll
                for (int c = 0; c < 5; c++) {
                    const float w = w5[r][c];
                    const uint2 u = s0[r * SW + c];
                    const __half2 h01 = *reinterpret_cast<const __half2*>(&u.x);
                    const __half2 h2p = *reinterpret_cast<const __half2*>(&u.y);
                    const float2 f01 = __half22float2(h01);
                    r0 += w * f01.x;
                    r1 += w * f01.y;
                    r2 += w * __low2float(h2p);
                }
            }
        } else {
            // ---- rare fallback (|flow| > halo but valid): fp32 global gathers.
            //      Kept un-unrolled and array-free to minimize register pressure.
            #pragma unroll 1
            for (int r = 0; r < 5; r++) {
                const int yy = min(max(iy - 1 + r, 0), H_ - 1);
                const float* g0 = ibase + yy * W_;
                #pragma unroll 1
                for (int c = 0; c < 5; c++) {
                    const int xo = min(max(ix - 1 + c, 0), W_ - 1);
                    const float w = w5[r][c];
                    r0 += w * __ldg(g0 + xo);
                    r1 += w * __ldg(g0 + xo + HW_);
                    r2 += w * __ldg(g0 + xo + 2 * HW_);
                }
            }
        }

        ob[0]       = r0;
        ob[HW_]     = r1;
        ob[2 * HW_] = r2;
    }
}

extern "C" void kernel_launch(void* const* d_in, const int* in_sizes, int n_in,
                              void* d_out, int out_size)
{
    const float* teninput  = (const float*)d_in[0];
    const float* tenflow   = (const float*)d_in[1];
    const float* tenfilter = (const float*)d_in[2];
    float* out = (float*)d_out;

    dim3 grid(W_ / TW, H_ / TH, B_);   // 15 x 32 x 4
    fi_tiled_h4o_kernel<<<grid, 256>>>(teninput, tenflow, tenfilter, out);
}

// round 5
// speedup vs baseline: 1.0685x; 1.0685x over previous
#include <cuda_runtime.h>
#include <cuda_fp16.h>

// Problem constants (fixed by the reference setup)
#define B_ 4
#define C_ 3
#define H_ 512
#define W_ 960
#define HW_ (H_ * W_)

// Tile geometry: 64x16 pixels per block, 256 threads, 4 pixels/thread (along y)
#define TW 64
#define TH 16
#define SW (TW + 13)          // 77 cols: halo 6 left, 7 right
#define SH (TH + 13)          // 29 rows: halo 6 top, 7 bottom
#define SPLANE (SW * SH)      // 2233 texels

__global__ void __launch_bounds__(256, 5)
fi_tiled_h5_kernel(const float* __restrict__ inp,
                   const float* __restrict__ flow,
                   const float* __restrict__ filt,
                   float* __restrict__ out)
{
    // one 8-byte texel per pixel: (half c0, half c1, half c2, pad)
    __shared__ uint2 sm[SPLANE];   // 17.9 KB

    const int x0 = blockIdx.x * TW;
    const int y0 = blockIdx.y * TH;
    const int b  = blockIdx.z;
    const int tid = threadIdx.x;

    const float* __restrict__ ibase = inp + (size_t)b * C_ * HW_;

    // ---- stage tile + halo into smem (border clamp baked in, fp32 -> fp16x3) ----
    #pragma unroll 3
    for (int idx = tid; idx < SPLANE; idx += 256) {
        const int j = idx / SW;
        const int i = idx - j * SW;
        const int gy = min(max(y0 - 6 + j, 0), H_ - 1);
        const int gx = min(max(x0 - 6 + i, 0), W_ - 1);
        const int g  = gy * W_ + gx;
        const float v0 = ibase[g];
        const float v1 = ibase[g + HW_];
        const float v2 = ibase[g + 2 * HW_];
        __half2 h01 = __floats2half2_rn(v0, v1);
        __half2 h2p = __floats2half2_rn(v2, 0.0f);
        uint2 u;
        u.x = *reinterpret_cast<unsigned*>(&h01);
        u.y = *reinterpret_cast<unsigned*>(&h2p);
        sm[idx] = u;
    }
    __syncthreads();

    const int x   = x0 + (tid & 63);
    const int tyg = tid >> 6;            // 0..3

    const float* __restrict__ flowx = flow + ((size_t)b * 2 + 0) * HW_;
    const float* __restrict__ flowy = flow + ((size_t)b * 2 + 1) * HW_;
    const float* __restrict__ fbb   = filt + (size_t)b * 16 * HW_;
    float* __restrict__ obb         = out  + (size_t)b * C_ * HW_;

    #pragma unroll
    for (int k = 0; k < 4; k++) {
        const int y   = y0 + tyg * 4 + k;
        const int pix = y * W_ + x;

        const float fx = flowx[pix];
        const float fy = flowy[pix];
        const float x2 = (float)x + fx;
        const float y2 = (float)y + fy;

        const bool valid =
            (x2 >= 0.0f) && (x2 <= (float)(W_ - 1)) &&
            (y2 >= 0.0f) && (y2 <= (float)(H_ - 1)) &&
            (fabsf(fx) < (float)W_ * 0.5f) &&
            (fabsf(fy) < (float)H_ * 0.5f);

        float* ob = obb + pix;
        if (!valid) {
            ob[0] = 0.0f; ob[HW_] = 0.0f; ob[2 * HW_] = 0.0f;
            continue;
        }

        const int   ix = (int)floorf(x2);
        const int   iy = (int)floorf(y2);
        const float a  = x2 - (float)ix;
        const float bt = y2 - (float)iy;

        const float wTL = (1.0f - a) * (1.0f - bt);
        const float wTR = a * (1.0f - bt);
        const float wBL = (1.0f - a) * bt;
        const float wBR = a * bt;

        // ---- preload 16 filter taps (early, wide MLP) ----
        float f[16];
        const float* fb = fbb + pix;
        #pragma unroll
        for (int t = 0; t < 16; t++) f[t] = __ldg(fb + t * HW_);

        float r0 = 0.0f, r1 = 0.0f, r2 = 0.0f;

        const int ly = iy - y0 + 5;   // smem row of window top (r=0)
        const int lx = ix - x0 + 5;   // smem col of window left (c=0)

        if (ly >= 0 && ly <= SH - 5 && lx >= 0 && lx <= SW - 5) {
            // ---- fast path: 25 taps, one LDS.64 each; tap weight computed
            //      on the fly from the 16 filter regs (no w5 array) ----
            const uint2* s0 = sm + ly * SW + lx;
            #pragma unroll
            for (int r = 0; r < 5; r++) {
                #pragma unroll
                for (int c = 0; c < 5; c++) {
                    float w = 0.0f;
                    if (r < 4 && c < 4)  w += wTL * f[r * 4 + c];
                    if (r < 4 && c >= 1) w += wTR * f[r * 4 + c - 1];
                    if (r >= 1 && c < 4) w += wBL * f[(r - 1) * 4 + c];
                    if (r >= 1 && c >= 1)w += wBR * f[(r - 1) * 4 + c - 1];

                    const uint2 u = s0[r * SW + c];
                    const __half2 h01 = *reinterpret_cast<const __half2*>(&u.x);
                    const __half2 h2p = *reinterpret_cast<const __half2*>(&u.y);
                    const float2 f01 = __half22float2(h01);
                    r0 += w * f01.x;
                    r1 += w * f01.y;
                    r2 += w * __low2float(h2p);
                }
            }
        } else {
            // ---- rare fallback (|flow| > halo but valid): fp32 global gathers ----
            #pragma unroll 1
            for (int r = 0; r < 5; r++) {
                const int yy = min(max(iy - 1 + r, 0), H_ - 1);
                const float* g0 = ibase + yy * W_;
                #pragma unroll 1
                for (int c = 0; c < 5; c++) {
                    float w = 0.0f;
                    if (r < 4 && c < 4)  w += wTL * f[r * 4 + c];
                    if (r < 4 && c >= 1) w += wTR * f[r * 4 + c - 1];
                    if (r >= 1 && c < 4) w += wBL * f[(r - 1) * 4 + c];
                    if (r >= 1 && c >= 1)w += wBR * f[(r - 1) * 4 + c - 1];

                    const int xo = min(max(ix - 1 + c, 0), W_ - 1);
                    r0 += w * __ldg(g0 + xo);
                    r1 += w * __ldg(g0 + xo + HW_);
                    r2 += w * __ldg(g0 + xo + 2 * HW_);
                }
            }
        }

        ob[0]       = r0;
        ob[HW_]     = r1;
        ob[2 * HW_] = r2;
    }
}

extern "C" void kernel_launch(void* const* d_in, const int* in_sizes, int n_in,
                              void* d_out, int out_size)
{
    const float* teninput  = (const float*)d_in[0];
    const float* tenflow   = (const float*)d_in[1];
    const float* tenfilter = (const float*)d_in[2];
    float* out = (float*)d_out;

    dim3 grid(W_ / TW, H_ / TH, B_);   // 15 x 32 x 4
    fi_tiled_h5_kernel<<<grid, 256>>>(teninput, tenflow, tenfilter, out);
}